// round 15
// baseline (speedup 1.0000x reference)
#include <cuda_runtime.h>
#include <cstdint>

// BoundaryOperator: out[r,:] += val * feat[c,:]  (SpMM, D=64 fp32)
// Fixed-stride int2 binning -> gather. R12 (resubmit after infra failure):
// exact R7 straight-line gather shape, but slab entries come from 16
// uniform-address broadcast LDGs (one 128B line, L1-broadcast) instead of
// lane-prefetch + 32 SHFLs. No branches between loads; feature loads
// predicated on j<n as before.

#define D_FEAT   64
#define K_MAX    16            // slots per row (128B slab of int2)
#define NV_CAP   524288        // max output rows supported by bin path
#define OVF_CAP  1048576       // overflow entries

__device__ int  g_counts[NV_CAP];
__device__ int2 g_bins[(size_t)NV_CAP * K_MAX];   // {col, float_bits(val)}
__device__ int4 g_ovf[OVF_CAP];                   // {row, col, valbits, pad}
__device__ int  g_ovf_count;

// ---------------- kernels ----------------

__global__ __launch_bounds__(512) void zero_counts_kernel(int n4) { // n4 = num_v/4
    for (int i = blockIdx.x * blockDim.x + threadIdx.x;
         i < n4; i += gridDim.x * blockDim.x)
        ((int4*)g_counts)[i] = make_int4(0, 0, 0, 0);
    if (blockIdx.x == 0 && threadIdx.x == 0) g_ovf_count = 0;
}

__device__ __forceinline__ void bin_one(int r, int c, float v) {
    int slot = atomicAdd(&g_counts[r], 1);
    if (slot < K_MAX) {
        g_bins[(size_t)r * K_MAX + slot] = make_int2(c, __float_as_int(v));
    } else {
        int o = atomicAdd(&g_ovf_count, 1);
        if (o < OVF_CAP) g_ovf[o] = make_int4(r, c, __float_as_int(v), 0);
    }
}

__global__ __launch_bounds__(256) void bin_kernel(
    const int*   __restrict__ rows,
    const int*   __restrict__ cols,
    const float* __restrict__ vals,
    int nnz)
{
    int t = blockIdx.x * blockDim.x + threadIdx.x;
    int base = t * 4;
    if (base + 3 < nnz) {
        int4   r4 = __ldcs((const int4*)  (rows + base));
        int4   c4 = __ldcs((const int4*)  (cols + base));
        float4 v4 = __ldcs((const float4*)(vals + base));
        bin_one(r4.x, c4.x, v4.x);
        bin_one(r4.y, c4.y, v4.y);
        bin_one(r4.z, c4.z, v4.z);
        bin_one(r4.w, c4.w, v4.w);
    } else if (base < nnz) {
        for (int i = base; i < nnz; i++)
            bin_one(__ldcs(&rows[i]), __ldcs(&cols[i]), __ldcs(&vals[i]));
    }
}

// one warp per output row; lane owns a float2 (32 lanes x 8B = 256B row).
__global__ __launch_bounds__(256) void gather_kernel(
    const float2* __restrict__ feat2,   // [NUM_E * 32]
    float2*       __restrict__ out2,    // [num_v * 32]
    int num_v)
{
    int warp = (blockIdx.x * blockDim.x + threadIdx.x) >> 5;
    int lane = threadIdx.x & 31;
    if (warp >= num_v) return;

    // count load issues in parallel with the slab-entry loads below
    int cnt = __ldcs(&g_counts[warp]);
    int n = cnt > K_MAX ? K_MAX : cnt;

    const int2* slab = &g_bins[(size_t)warp * K_MAX];

    // 16 independent uniform-address loads: one 128B line fetch, then
    // L1-broadcast. No shuffles, no branches. Garbage entries (j >= n)
    // are never dereferenced (feature load predicated).
    int2 e[K_MAX];
    #pragma unroll
    for (int j = 0; j < K_MAX; j++)
        e[j] = slab[j];

    float2 acc = make_float2(0.f, 0.f);
    #pragma unroll
    for (int j = 0; j < K_MAX; j++) {
        if (j < n) {
            float2 f = feat2[(size_t)e[j].x * 32 + lane];
            float v = __int_as_float(e[j].y);
            acc.x = fmaf(v, f.x, acc.x);
            acc.y = fmaf(v, f.y, acc.y);
        }
    }

    if (cnt > K_MAX) {                   // rare: scan overflow list inline
        int total = g_ovf_count;
        if (total > OVF_CAP) total = OVF_CAP;
        for (int i = 0; i < total; i++) {
            int4 o = g_ovf[i];
            if (o.x == warp) {
                float v = __int_as_float(o.z);
                float2 f = feat2[(size_t)o.y * 32 + lane];
                acc.x = fmaf(v, f.x, acc.x);
                acc.y = fmaf(v, f.y, acc.y);
            }
        }
    }

    // streaming (evict-first) full-line write: keep features in L2
    float2* p = out2 + (size_t)warp * 32 + lane;
    asm volatile("st.global.cs.v2.f32 [%0], {%1, %2};"
                 :: "l"(p), "f"(acc.x), "f"(acc.y) : "memory");
}

// ---------------- fallback (proven R1 atomic path) ----------------

__global__ void zero_out_kernel(float4* __restrict__ out4, int n4) {
    int i = blockIdx.x * blockDim.x + threadIdx.x;
    if (i < n4) out4[i] = make_float4(0.f, 0.f, 0.f, 0.f);
}

__global__ __launch_bounds__(256) void spmm_scatter_kernel(
    const float4* __restrict__ feat4, const float* __restrict__ vals,
    const int* __restrict__ rows, const int* __restrict__ cols,
    float* __restrict__ out, int nnz)
{
    int i = blockIdx.x * blockDim.x + threadIdx.x;
    int e = i >> 4;
    if (e >= nnz) return;
    int chunk = i & 15;
    int   r = rows[e];
    int   c = cols[e];
    float v = vals[e];
    float4 f = feat4[(size_t)c * 16 + chunk];
    float* p = out + (size_t)r * D_FEAT + chunk * 4;
    asm volatile("red.global.add.v4.f32 [%0], {%1, %2, %3, %4};"
                 :: "l"(p), "f"(v * f.x), "f"(v * f.y), "f"(v * f.z), "f"(v * f.w)
                 : "memory");
}

extern "C" void kernel_launch(void* const* d_in, const int* in_sizes, int n_in,
                              void* d_out, int out_size) {
    const float* feat = (const float*)d_in[0];
    const float* vals = (const float*)d_in[1];
    const int*   rows = (const int*)  d_in[2];
    const int*   cols = (const int*)  d_in[3];
    float*       out  = (float*)      d_out;

    int nnz   = in_sizes[1];
    int num_v = out_size / D_FEAT;

    if (num_v > NV_CAP || num_v <= 0 || nnz <= 0 || (num_v & 3) != 0) {
        int n4 = out_size / 4;
        zero_out_kernel<<<(n4 + 255) / 256, 256>>>((float4*)out, n4);
        if (nnz > 0) {
            long long total = (long long)nnz * 16;
            spmm_scatter_kernel<<<(int)((total + 255) / 256), 256>>>(
                (const float4*)feat, vals, rows, cols, out, nnz);
        }
        return;
    }

    zero_counts_kernel<<<296, 512>>>(num_v / 4);

    int nthreads_bin = (nnz + 3) / 4;
    bin_kernel<<<(nthreads_bin + 255) / 256, 256>>>(rows, cols, vals, nnz);

    long long gthreads = (long long)num_v * 32;
    gather_kernel<<<(int)((gthreads + 255) / 256), 256>>>(
        (const float2*)feat, (float2*)out, num_v);
}

// round 16
// speedup vs baseline: 1.2433x; 1.2433x over previous
#include <cuda_runtime.h>
#include <cstdint>

// BoundaryOperator: out[r,:] += val * feat[c,:]  (SpMM, D=64 fp32)
// CHAMPION config (215us): fixed-stride int2 binning -> gather with
// lane slab-prefetch + shuffle broadcast, straight-line predicated feature
// loads (count/slab loads independent), streaming output write.
// R15 delta vs champion: gather block size 256 -> 512 (launch config only).

#define D_FEAT   64
#define K_MAX    16            // slots per row (128B slab of int2)
#define NV_CAP   524288        // max output rows supported by bin path
#define OVF_CAP  1048576       // overflow entries

__device__ int  g_counts[NV_CAP];
__device__ int2 g_bins[(size_t)NV_CAP * K_MAX];   // {col, float_bits(val)}
__device__ int4 g_ovf[OVF_CAP];                   // {row, col, valbits, pad}
__device__ int  g_ovf_count;

// ---------------- kernels ----------------

__global__ __launch_bounds__(512) void zero_counts_kernel(int n4) { // n4 = num_v/4
    for (int i = blockIdx.x * blockDim.x + threadIdx.x;
         i < n4; i += gridDim.x * blockDim.x)
        ((int4*)g_counts)[i] = make_int4(0, 0, 0, 0);
    if (blockIdx.x == 0 && threadIdx.x == 0) g_ovf_count = 0;
}

__device__ __forceinline__ void bin_one(int r, int c, float v) {
    int slot = atomicAdd(&g_counts[r], 1);
    if (slot < K_MAX) {
        g_bins[(size_t)r * K_MAX + slot] = make_int2(c, __float_as_int(v));
    } else {
        int o = atomicAdd(&g_ovf_count, 1);
        if (o < OVF_CAP) g_ovf[o] = make_int4(r, c, __float_as_int(v), 0);
    }
}

__global__ __launch_bounds__(256) void bin_kernel(
    const int*   __restrict__ rows,
    const int*   __restrict__ cols,
    const float* __restrict__ vals,
    int nnz)
{
    int t = blockIdx.x * blockDim.x + threadIdx.x;
    int base = t * 4;
    if (base + 3 < nnz) {
        int4   r4 = __ldcs((const int4*)  (rows + base));
        int4   c4 = __ldcs((const int4*)  (cols + base));
        float4 v4 = __ldcs((const float4*)(vals + base));
        bin_one(r4.x, c4.x, v4.x);
        bin_one(r4.y, c4.y, v4.y);
        bin_one(r4.z, c4.z, v4.z);
        bin_one(r4.w, c4.w, v4.w);
    } else if (base < nnz) {
        for (int i = base; i < nnz; i++)
            bin_one(__ldcs(&rows[i]), __ldcs(&cols[i]), __ldcs(&vals[i]));
    }
}

// one warp per output row; lane owns a float2 (32 lanes x 8B = 256B row).
__global__ __launch_bounds__(512) void gather_kernel(
    const float2* __restrict__ feat2,   // [NUM_E * 32]
    float2*       __restrict__ out2,    // [num_v * 32]
    int num_v)
{
    int warp = (blockIdx.x * blockDim.x + threadIdx.x) >> 5;
    int lane = threadIdx.x & 31;
    if (warp >= num_v) return;

    // Independent loads: count and full slab issue together.
    int cnt = __ldcs(&g_counts[warp]);   // broadcast, read-once
    int2 mine = make_int2(0, 0);
    if (lane < K_MAX)                    // NOT dependent on cnt
        mine = __ldcs(&g_bins[(size_t)warp * K_MAX + lane]);

    int n = cnt > K_MAX ? K_MAX : cnt;

    // broadcast entries to all lanes (fixed-count, fully unrolled)
    int   cs[K_MAX];
    float vs[K_MAX];
    #pragma unroll
    for (int j = 0; j < K_MAX; j++) {
        cs[j] = __shfl_sync(0xffffffffu, mine.x, j);
        vs[j] = __int_as_float(__shfl_sync(0xffffffffu, mine.y, j));
    }

    // predicated, unrolled: all feature loads independent -> MLP = n
    float2 acc = make_float2(0.f, 0.f);
    #pragma unroll
    for (int j = 0; j < K_MAX; j++) {
        if (j < n) {
            float2 f = feat2[(size_t)cs[j] * 32 + lane];
            acc.x = fmaf(vs[j], f.x, acc.x);
            acc.y = fmaf(vs[j], f.y, acc.y);
        }
    }

    if (cnt > K_MAX) {                   // rare: scan overflow list inline
        int total = g_ovf_count;
        if (total > OVF_CAP) total = OVF_CAP;
        for (int i = 0; i < total; i++) {
            int4 e = g_ovf[i];
            if (e.x == warp) {
                float v = __int_as_float(e.z);
                float2 f = feat2[(size_t)e.y * 32 + lane];
                acc.x = fmaf(v, f.x, acc.x);
                acc.y = fmaf(v, f.y, acc.y);
            }
        }
    }

    // streaming (evict-first) full-line write: keep features in L2
    float2* p = out2 + (size_t)warp * 32 + lane;
    asm volatile("st.global.cs.v2.f32 [%0], {%1, %2};"
                 :: "l"(p), "f"(acc.x), "f"(acc.y) : "memory");
}

// ---------------- fallback (proven R1 atomic path) ----------------

__global__ void zero_out_kernel(float4* __restrict__ out4, int n4) {
    int i = blockIdx.x * blockDim.x + threadIdx.x;
    if (i < n4) out4[i] = make_float4(0.f, 0.f, 0.f, 0.f);
}

__global__ __launch_bounds__(256) void spmm_scatter_kernel(
    const float4* __restrict__ feat4, const float* __restrict__ vals,
    const int* __restrict__ rows, const int* __restrict__ cols,
    float* __restrict__ out, int nnz)
{
    int i = blockIdx.x * blockDim.x + threadIdx.x;
    int e = i >> 4;
    if (e >= nnz) return;
    int chunk = i & 15;
    int   r = rows[e];
    int   c = cols[e];
    float v = vals[e];
    float4 f = feat4[(size_t)c * 16 + chunk];
    float* p = out + (size_t)r * D_FEAT + chunk * 4;
    asm volatile("red.global.add.v4.f32 [%0], {%1, %2, %3, %4};"
                 :: "l"(p), "f"(v * f.x), "f"(v * f.y), "f"(v * f.z), "f"(v * f.w)
                 : "memory");
}

extern "C" void kernel_launch(void* const* d_in, const int* in_sizes, int n_in,
                              void* d_out, int out_size) {
    const float* feat = (const float*)d_in[0];
    const float* vals = (const float*)d_in[1];
    const int*   rows = (const int*)  d_in[2];
    const int*   cols = (const int*)  d_in[3];
    float*       out  = (float*)      d_out;

    int nnz   = in_sizes[1];
    int num_v = out_size / D_FEAT;

    if (num_v > NV_CAP || num_v <= 0 || nnz <= 0 || (num_v & 3) != 0) {
        int n4 = out_size / 4;
        zero_out_kernel<<<(n4 + 255) / 256, 256>>>((float4*)out, n4);
        if (nnz > 0) {
            long long total = (long long)nnz * 16;
            spmm_scatter_kernel<<<(int)((total + 255) / 256), 256>>>(
                (const float4*)feat, vals, rows, cols, out, nnz);
        }
        return;
    }

    zero_counts_kernel<<<296, 512>>>(num_v / 4);

    int nthreads_bin = (nnz + 3) / 4;
    bin_kernel<<<(nthreads_bin + 255) / 256, 256>>>(rows, cols, vals, nnz);

    long long gthreads = (long long)num_v * 32;
    gather_kernel<<<(int)((gthreads + 511) / 512), 512>>>(
        (const float2*)feat, (float2*)out, num_v);
}

// round 17
// speedup vs baseline: 1.3141x; 1.0570x over previous
#include <cuda_runtime.h>
#include <cstdint>

// BoundaryOperator: out[r,:] += val * feat[c,:]  (SpMM, D=64 fp32)
// CHAMPION (215us verified): fixed-stride int2 binning -> gather with lane
// slab-prefetch + shuffle broadcast, straight-line predicated feature loads
// (count/slab loads independent -> parallel issue), streaming output write.
// Prep: vectorized bin kernel (4 nnz/thread), grid-stride vectorized zeroing.

#define D_FEAT   64
#define K_MAX    16            // slots per row (128B slab of int2)
#define NV_CAP   524288        // max output rows supported by bin path
#define OVF_CAP  1048576       // overflow entries

__device__ int  g_counts[NV_CAP];
__device__ int2 g_bins[(size_t)NV_CAP * K_MAX];   // {col, float_bits(val)}
__device__ int4 g_ovf[OVF_CAP];                   // {row, col, valbits, pad}
__device__ int  g_ovf_count;

// ---------------- kernels ----------------

__global__ __launch_bounds__(512) void zero_counts_kernel(int n4) { // n4 = num_v/4
    for (int i = blockIdx.x * blockDim.x + threadIdx.x;
         i < n4; i += gridDim.x * blockDim.x)
        ((int4*)g_counts)[i] = make_int4(0, 0, 0, 0);
    if (blockIdx.x == 0 && threadIdx.x == 0) g_ovf_count = 0;
}

__device__ __forceinline__ void bin_one(int r, int c, float v) {
    int slot = atomicAdd(&g_counts[r], 1);
    if (slot < K_MAX) {
        g_bins[(size_t)r * K_MAX + slot] = make_int2(c, __float_as_int(v));
    } else {
        int o = atomicAdd(&g_ovf_count, 1);
        if (o < OVF_CAP) g_ovf[o] = make_int4(r, c, __float_as_int(v), 0);
    }
}

__global__ __launch_bounds__(256) void bin_kernel(
    const int*   __restrict__ rows,
    const int*   __restrict__ cols,
    const float* __restrict__ vals,
    int nnz)
{
    int t = blockIdx.x * blockDim.x + threadIdx.x;
    int base = t * 4;
    if (base + 3 < nnz) {
        int4   r4 = __ldcs((const int4*)  (rows + base));
        int4   c4 = __ldcs((const int4*)  (cols + base));
        float4 v4 = __ldcs((const float4*)(vals + base));
        bin_one(r4.x, c4.x, v4.x);
        bin_one(r4.y, c4.y, v4.y);
        bin_one(r4.z, c4.z, v4.z);
        bin_one(r4.w, c4.w, v4.w);
    } else if (base < nnz) {
        for (int i = base; i < nnz; i++)
            bin_one(__ldcs(&rows[i]), __ldcs(&cols[i]), __ldcs(&vals[i]));
    }
}

// one warp per output row; lane owns a float2 (32 lanes x 8B = 256B row).
__global__ __launch_bounds__(256) void gather_kernel(
    const float2* __restrict__ feat2,   // [NUM_E * 32]
    float2*       __restrict__ out2,    // [num_v * 32]
    int num_v)
{
    int warp = (blockIdx.x * blockDim.x + threadIdx.x) >> 5;
    int lane = threadIdx.x & 31;
    if (warp >= num_v) return;

    // Independent loads: count and full slab issue together.
    int cnt = __ldcs(&g_counts[warp]);   // broadcast, read-once
    int2 mine = make_int2(0, 0);
    if (lane < K_MAX)                    // NOT dependent on cnt
        mine = __ldcs(&g_bins[(size_t)warp * K_MAX + lane]);

    int n = cnt > K_MAX ? K_MAX : cnt;

    // broadcast entries to all lanes (fixed-count, fully unrolled)
    int   cs[K_MAX];
    float vs[K_MAX];
    #pragma unroll
    for (int j = 0; j < K_MAX; j++) {
        cs[j] = __shfl_sync(0xffffffffu, mine.x, j);
        vs[j] = __int_as_float(__shfl_sync(0xffffffffu, mine.y, j));
    }

    // predicated, unrolled: all feature loads independent -> MLP = n
    float2 acc = make_float2(0.f, 0.f);
    #pragma unroll
    for (int j = 0; j < K_MAX; j++) {
        if (j < n) {
            float2 f = feat2[(size_t)cs[j] * 32 + lane];
            acc.x = fmaf(vs[j], f.x, acc.x);
            acc.y = fmaf(vs[j], f.y, acc.y);
        }
    }

    if (cnt > K_MAX) {                   // rare: scan overflow list inline
        int total = g_ovf_count;
        if (total > OVF_CAP) total = OVF_CAP;
        for (int i = 0; i < total; i++) {
            int4 e = g_ovf[i];
            if (e.x == warp) {
                float v = __int_as_float(e.z);
                float2 f = feat2[(size_t)e.y * 32 + lane];
                acc.x = fmaf(v, f.x, acc.x);
                acc.y = fmaf(v, f.y, acc.y);
            }
        }
    }

    // streaming (evict-first) full-line write: keep features in L2
    float2* p = out2 + (size_t)warp * 32 + lane;
    asm volatile("st.global.cs.v2.f32 [%0], {%1, %2};"
                 :: "l"(p), "f"(acc.x), "f"(acc.y) : "memory");
}

// ---------------- fallback (proven R1 atomic path) ----------------

__global__ void zero_out_kernel(float4* __restrict__ out4, int n4) {
    int i = blockIdx.x * blockDim.x + threadIdx.x;
    if (i < n4) out4[i] = make_float4(0.f, 0.f, 0.f, 0.f);
}

__global__ __launch_bounds__(256) void spmm_scatter_kernel(
    const float4* __restrict__ feat4, const float* __restrict__ vals,
    const int* __restrict__ rows, const int* __restrict__ cols,
    float* __restrict__ out, int nnz)
{
    int i = blockIdx.x * blockDim.x + threadIdx.x;
    int e = i >> 4;
    if (e >= nnz) return;
    int chunk = i & 15;
    int   r = rows[e];
    int   c = cols[e];
    float v = vals[e];
    float4 f = feat4[(size_t)c * 16 + chunk];
    float* p = out + (size_t)r * D_FEAT + chunk * 4;
    asm volatile("red.global.add.v4.f32 [%0], {%1, %2, %3, %4};"
                 :: "l"(p), "f"(v * f.x), "f"(v * f.y), "f"(v * f.z), "f"(v * f.w)
                 : "memory");
}

extern "C" void kernel_launch(void* const* d_in, const int* in_sizes, int n_in,
                              void* d_out, int out_size) {
    const float* feat = (const float*)d_in[0];
    const float* vals = (const float*)d_in[1];
    const int*   rows = (const int*)  d_in[2];
    const int*   cols = (const int*)  d_in[3];
    float*       out  = (float*)      d_out;

    int nnz   = in_sizes[1];
    int num_v = out_size / D_FEAT;

    if (num_v > NV_CAP || num_v <= 0 || nnz <= 0 || (num_v & 3) != 0) {
        int n4 = out_size / 4;
        zero_out_kernel<<<(n4 + 255) / 256, 256>>>((float4*)out, n4);
        if (nnz > 0) {
            long long total = (long long)nnz * 16;
            spmm_scatter_kernel<<<(int)((total + 255) / 256), 256>>>(
                (const float4*)feat, vals, rows, cols, out, nnz);
        }
        return;
    }

    zero_counts_kernel<<<296, 512>>>(num_v / 4);

    int nthreads_bin = (nnz + 3) / 4;
    bin_kernel<<<(nthreads_bin + 255) / 256, 256>>>(rows, cols, vals, nnz);

    long long gthreads = (long long)num_v * 32;
    gather_kernel<<<(int)((gthreads + 255) / 256), 256>>>(
        (const float2*)feat, (float2*)out, num_v);
}